// round 1
// baseline (speedup 1.0000x reference)
#include <cuda_runtime.h>
#include <cuda_bf16.h>
#include <math_constants.h>

// ---------------- problem constants ----------------
#define B      32
#define S      64
#define E      128
#define TSTEP  256
#define V      32000
#define ROWS   (B*TSTEP)          // 8192

// ---------------- scratch (device globals; no allocs allowed) ----------------
__device__ float g_scores[B * S * S];        // (b, s, t)
__device__ float g_xtran [B * S * S];        // (b, s, t)
__device__ float g_att0  [B * S];
__device__ float g_A     [B * TSTEP * S];    // att history (b, t, s)
__device__ float g_zs    [B * TSTEP * E];    // emitted states (row-major rows=b*256+t)

// ---------------- helpers ----------------
__device__ __forceinline__ void fma2(unsigned long long &d, unsigned long long a, unsigned long long b) {
    asm("fma.rn.f32x2 %0, %1, %2, %0;" : "+l"(d) : "l"(a), "l"(b));
}
__device__ __forceinline__ float lo32(unsigned long long v) { return __int_as_float((int)(unsigned)v); }
__device__ __forceinline__ float hi32(unsigned long long v) { return __int_as_float((int)(unsigned)(v >> 32)); }

// ================= Kernel A1: scores[b][s][t] = <xq_s, xk_t>/sqrt(E) =================
__global__ void kA1(const float* __restrict__ latent, const int* __restrict__ zi) {
    __shared__ float xkS[64 * 129];
    int b = blockIdx.x, tid = threadIdx.x;
    const float* xq = latent + (size_t)zi[(b >> 2)]      * 32768 + (size_t)(b & 3) * 8192;
    const float* xk = latent + (size_t)zi[8 + (b >> 2)]  * 32768 + (size_t)(b & 3) * 8192;
    for (int idx = tid; idx < 8192; idx += 256)
        xkS[(idx >> 7) * 129 + (idx & 127)] = __ldg(xk + idx);
    __syncthreads();
    int t = tid & 63, sg = tid >> 6;
    for (int i = 0; i < 16; i++) {
        int s = sg + 4 * i;
        float acc = 0.f;
        const float4* qp = (const float4*)(xq + s * 128);
        #pragma unroll 8
        for (int e4 = 0; e4 < 32; e4++) {
            float4 q = __ldg(qp + e4);
            const float* kp = &xkS[t * 129 + e4 * 4];
            acc += q.x * kp[0] + q.y * kp[1] + q.z * kp[2] + q.w * kp[3];
        }
        g_scores[b * 4096 + s * 64 + t] = acc * 0.08838834764831843f; // 1/sqrt(128)
    }
}

// ================= Kernel A2: column softmax -> xtran; att0 =================
__global__ void kA2(const float* __restrict__ latent, const int* __restrict__ zi) {
    int b = blockIdx.x, t = threadIdx.x; // 64 threads
    const float* col = g_scores + b * 4096 + t;
    float mx = -CUDART_INF_F;
    for (int s = 0; s < 64; s++) mx = fmaxf(mx, col[s * 64]);
    float sum = 0.f;
    for (int s = 0; s < 64; s++) {
        float e = __expf(col[s * 64] - mx);
        g_xtran[b * 4096 + s * 64 + t] = e;
        sum += e;
    }
    float inv = 1.f / sum;
    for (int s = 0; s < 64; s++) g_xtran[b * 4096 + s * 64 + t] *= inv;

    // att0 = softmax over s of xi[b][s][0]
    const float* ip = latent + (size_t)zi[24 + (b >> 2)] * 32768 + (size_t)(b & 3) * 8192;
    float xi = __ldg(ip + t * 128);
    __shared__ float smv[64];
    smv[t] = xi; __syncthreads();
    float m2 = -CUDART_INF_F;
    for (int s = 0; s < 64; s++) m2 = fmaxf(m2, smv[s]);
    float e2 = __expf(xi - m2);
    __syncthreads(); smv[t] = e2; __syncthreads();
    float su = 0.f;
    for (int s = 0; s < 64; s++) su += smv[s];
    g_att0[b * 64 + t] = e2 / su;
}

// ================= Kernel B: recurrence att_{t+1} = att_t @ xtran; zs = A @ xv ==========
__global__ __launch_bounds__(256) void kB(const float* __restrict__ latent, const int* __restrict__ zi) {
    __shared__ float xvS[64 * 128];
    __shared__ float attS[2][64];
    __shared__ float red[256];
    __shared__ float As[32 * 64];
    int b = blockIdx.x, tid = threadIdx.x;
    const float* xv = latent + (size_t)zi[16 + (b >> 2)] * 32768 + (size_t)(b & 3) * 8192;
    for (int idx = tid; idx < 8192; idx += 256) xvS[idx] = __ldg(xv + idx);

    int tp = tid & 63, c = tid >> 6;
    float xtc[16];
    #pragma unroll
    for (int i = 0; i < 16; i++) xtc[i] = g_xtran[b * 4096 + (c * 16 + i) * 64 + tp];
    if (tid < 64) attS[0][tid] = g_att0[b * 64 + tid];
    __syncthreads();

    int p = 0;
    for (int t = 0; t < 256; t++) {
        float partial = 0.f;
        #pragma unroll
        for (int i = 0; i < 16; i++) partial += attS[p][c * 16 + i] * xtc[i];
        red[tid] = partial;
        __syncthreads();
        if (c == 0) {
            g_A[(b * 256 + t) * 64 + tp] = attS[p][tp];
            attS[p ^ 1][tp] = red[tp] + red[64 + tp] + red[128 + tp] + red[192 + tp];
        }
        __syncthreads();
        p ^= 1;
    }

    // phase 2: zs[b][t][e] = sum_s A[t][s]*xv[s][e]
    int e = tid & 127, h = tid >> 7;
    for (int tb = 0; tb < 8; tb++) {
        __syncthreads();
        for (int k = tid; k < 2048; k += 256) As[k] = g_A[(b * 256 + tb * 32) * 64 + k];
        __syncthreads();
        for (int i = 0; i < 16; i++) {
            int tl = h * 16 + i;
            float acc = 0.f;
            #pragma unroll
            for (int s2 = 0; s2 < 64; s2++) acc += As[tl * 64 + s2] * xvS[s2 * 128 + e];
            g_zs[((size_t)b * 256 + tb * 32 + tl) * 128 + e] = acc;
        }
    }
}

// ================= Kernel C: fused logits GEMM + online logsumexp + gather ==============
// CTA: 32 rows x full vocab (chunks of 128). threads 256: tx=vocab lane, ty=row group(4 rows)
#define WPITCH 132
#define SMEM_C ((4096 + 16896 + 128) * 4)

__global__ __launch_bounds__(256, 2) void kC(const float* __restrict__ vw,
                                             const float* __restrict__ vb,
                                             const int*   __restrict__ y,
                                             float*       __restrict__ out) {
    extern __shared__ float sm[];
    float* zsS = sm;            // 32*128
    float* wS  = sm + 4096;     // 128*132
    float* bS  = wS + 16896;    // 128

    int tid = threadIdx.x;
    int tx = tid & 31, ty = tid >> 5;
    int rowbase = blockIdx.x * 32;

    // load zs tile (32 rows, contiguous)
    {
        const float4* zg = (const float4*)(g_zs + (size_t)rowbase * 128);
        float4* zd = (float4*)zsS;
        #pragma unroll
        for (int k = 0; k < 4; k++) zd[tid + 256 * k] = __ldg(zg + tid + 256 * k);
    }

    int   ytgt[4];
    float m[4], s[4], tg[4];
    #pragma unroll
    for (int j = 0; j < 4; j++) {
        ytgt[j] = __ldg(y + rowbase + ty * 4 + j);
        m[j] = -CUDART_INF_F; s[j] = 0.f; tg[j] = 0.f;
    }

    for (int cch = 0; cch < 250; cch++) {
        int vbase = cch * 128;
        __syncthreads();   // previous compute done before overwriting wS/bS; also first-iter zs fence
        // load vocab chunk: 128 rows into pitch-132 smem, fully coalesced
        const float4* wg = (const float4*)(vw + (size_t)vbase * 128);
        #pragma unroll
        for (int k = 0; k < 16; k++) {
            int idx = tid + 256 * k;
            int v = idx >> 5, f = idx & 31;
            float4 val = __ldg(wg + idx);
            *(float4*)&wS[v * WPITCH + f * 4] = val;
        }
        if (tid < 128) bS[tid] = __ldg(vb + vbase + tid);
        __syncthreads();

        unsigned long long acc[4][4];
        #pragma unroll
        for (int j = 0; j < 4; j++)
            #pragma unroll
            for (int jj = 0; jj < 4; jj++) acc[j][jj] = 0ULL;

        #pragma unroll 4
        for (int e4 = 0; e4 < 32; e4++) {
            ulonglong2 wq[4];
            #pragma unroll
            for (int jj = 0; jj < 4; jj++)
                wq[jj] = *(const ulonglong2*)&wS[(tx + 32 * jj) * WPITCH + e4 * 4];
            #pragma unroll
            for (int j = 0; j < 4; j++) {
                ulonglong2 zq = *(const ulonglong2*)&zsS[(ty * 4 + j) * 128 + e4 * 4];
                #pragma unroll
                for (int jj = 0; jj < 4; jj++) {
                    fma2(acc[j][jj], zq.x, wq[jj].x);
                    fma2(acc[j][jj], zq.y, wq[jj].y);
                }
            }
        }

        // epilogue: 4 complete logits per row -> online logsumexp + target capture
        #pragma unroll
        for (int j = 0; j < 4; j++) {
            float v0 = lo32(acc[j][0]) + hi32(acc[j][0]) + bS[tx];
            float v1 = lo32(acc[j][1]) + hi32(acc[j][1]) + bS[tx + 32];
            float v2 = lo32(acc[j][2]) + hi32(acc[j][2]) + bS[tx + 64];
            float v3 = lo32(acc[j][3]) + hi32(acc[j][3]) + bS[tx + 96];
            int vg = vbase + tx;
            tg[j] += (vg      == ytgt[j]) ? v0 : 0.f;
            tg[j] += (vg + 32 == ytgt[j]) ? v1 : 0.f;
            tg[j] += (vg + 64 == ytgt[j]) ? v2 : 0.f;
            tg[j] += (vg + 96 == ytgt[j]) ? v3 : 0.f;
            float ml = fmaxf(fmaxf(v0, v1), fmaxf(v2, v3));
            float mn = fmaxf(m[j], ml);
            s[j] = s[j] * __expf(m[j] - mn)
                 + __expf(v0 - mn) + __expf(v1 - mn) + __expf(v2 - mn) + __expf(v3 - mn);
            m[j] = mn;
        }
    }

    // warp reduce across 32 vocab lanes
    #pragma unroll
    for (int j = 0; j < 4; j++) {
        #pragma unroll
        for (int off = 16; off; off >>= 1) {
            float mo = __shfl_xor_sync(0xffffffffu, m[j],  off);
            float so = __shfl_xor_sync(0xffffffffu, s[j],  off);
            float to = __shfl_xor_sync(0xffffffffu, tg[j], off);
            float mn = fmaxf(m[j], mo);
            s[j] = s[j] * __expf(m[j] - mn) + so * __expf(mo - mn);
            m[j] = mn;
            tg[j] += to;
        }
        if (tx == 0)
            out[rowbase + ty * 4 + j] = tg[j] - (m[j] + logf(s[j]));
    }
}

// ================= launch =================
extern "C" void kernel_launch(void* const* d_in, const int* in_sizes, int n_in,
                              void* d_out, int out_size) {
    const float* latent = (const float*)d_in[0];
    const float* vw     = (const float*)d_in[1];
    const float* vb     = (const float*)d_in[2];
    const int*   zi     = (const int*)d_in[3];
    const int*   y      = (const int*)d_in[4];
    float* out = (float*)d_out;

    kA1<<<B, 256>>>(latent, zi);
    kA2<<<B, 64>>>(latent, zi);
    kB <<<B, 256>>>(latent, zi);

    cudaFuncSetAttribute(kC, cudaFuncAttributeMaxDynamicSharedMemorySize, SMEM_C);
    kC<<<ROWS / 32, 256, SMEM_C>>>(vw, vb, y, out);
}